// round 5
// baseline (speedup 1.0000x reference)
#include <cuda_runtime.h>

#define IMG 28
#define IMG2 784              // 28*28
#define VPI 196               // float4 vectors per image
#define THREADS 224           // 7 warps; lanes 196..223 exit
#define BLOCKS_PER_SM 8
#define NSM 148

__global__ __launch_bounds__(THREADS, BLOCKS_PER_SM)
void sr_persist_kernel(const float4* __restrict__ x4,
                       const int*    __restrict__ t,
                       const float*  __restrict__ Wk,
                       const float*  __restrict__ bias,
                       float4* __restrict__ out4,
                       int B)
{
    const int tx = threadIdx.x;
    if (tx >= VPI) return;

    // ---- geometry hoisted out of the loop: fixed per thread ----
    const int row  = tx / 7;
    const int col0 = (tx - row * 7) * 4;
    const int dr   = row - 14;
    const int dr2  = dr * dr;
    int d2[4];
    #pragma unroll
    for (int k = 0; k < 4; ++k) {
        const int dc = col0 + k - 14;
        d2[k] = dr2 + dc * dc;
    }

    const int stride = gridDim.x;
    int img = blockIdx.x;
    if (img >= B) return;

    // ---- software pipeline: prefetch image i+stride while processing i ----
    float4 v  = x4[(size_t)img * VPI + tx];
    int    tv = __ldg(&t[img]);

    while (img < B) {
        const int next = img + stride;
        float4 cur = v;
        const int tvc = tv;
        if (next < B) {                       // issue next loads early
            v  = x4[(size_t)next * VPI + tx];
            tv = __ldg(&t[next]);
        }

        const int hi = tvc * tvc;
        const int lo = (tvc >= 1) ? (tvc - 1) * (tvc - 1) : -1;

        float* res = reinterpret_cast<float*>(&cur);
        #pragma unroll
        for (int k = 0; k < 4; ++k) {
            if (d2[k] <= hi && d2[k] > lo) {  // rare annulus path
                const float* base = (const float*)x4 + (size_t)img * IMG2;
                const int col = col0 + k;
                float acc = __ldg(bias);
                #pragma unroll
                for (int ki = 0; ki < 3; ++ki) {
                    const int r = row + ki - 1;
                    if (r < 0 || r >= IMG) continue;
                    #pragma unroll
                    for (int kj = 0; kj < 3; ++kj) {
                        const int c = col + kj - 1;
                        if (c < 0 || c >= IMG) continue;
                        acc += base[r * IMG + c] * __ldg(&Wk[ki * 3 + kj]);
                    }
                }
                res[k] += acc;
            }
        }

        out4[(size_t)img * VPI + tx] = cur;
        img = next;
    }
}

extern "C" void kernel_launch(void* const* d_in, const int* in_sizes, int n_in,
                              void* d_out, int out_size)
{
    const float4* x4   = (const float4*)d_in[0];  // [B,1,28,28] f32
    const int*    t    = (const int*)   d_in[1];  // [B] i32
    const float*  Wk   = (const float*) d_in[2];  // [1,1,3,3] f32
    const float*  bias = (const float*) d_in[3];  // [1] f32
    float4* out4 = (float4*)d_out;

    const int B = in_sizes[1];
    int grid = NSM * BLOCKS_PER_SM;               // persistent
    if (grid > B) grid = B;
    sr_persist_kernel<<<grid, THREADS>>>(x4, t, Wk, bias, out4, B);
}